// round 3
// baseline (speedup 1.0000x reference)
#include <cuda_runtime.h>
#include <cuda_bf16.h>

// ---- static problem config ----
#define NIMG 32
#define HH   1024
#define WW   1024
#define BHW  16                 // pool window
#define BSTR 14                 // block stride
#define BC   73                 // blocks per spatial dim
#define NROW (NIMG*BC)          // 2336  (n, bh) row-blocks
#define NBLK (NROW*BC)          // 170528 total blocks
#define OUT_ELEMS (NBLK*3)      // 511584 output elements
#define THRESH 0.9f

// scratch (device globals — no allocation allowed)
__device__ int g_flags[NBLK];
__device__ int g_pos[NBLK];

// ---------------------------------------------------------------------------
// K0: fill output with -1.0f (nonzero() padding value, as float32 output).
// ---------------------------------------------------------------------------
__global__ __launch_bounds__(256) void fill_kernel(float* __restrict__ out)
{
    int i = blockIdx.x * 256 + threadIdx.x;
    if (i < OUT_ELEMS) out[i] = -1.0f;
}

// ---------------------------------------------------------------------------
// K1: one CTA per (n, bh). 256 threads compute the vertical max over the
// <=16-row window with coalesced float4 loads (4 columns per thread), stash
// per-column maxima in smem, then 73 threads compute the horizontal window
// max and emit a 0/1 flag per pooled block. Zero is the exact identity:
// the reference pads with zeros and mask values lie in [0,1).
// ---------------------------------------------------------------------------
__global__ __launch_bounds__(256) void pool_kernel(const float* __restrict__ mask)
{
    const int cta = blockIdx.x;          // n*BC + bh
    const int n   = cta / BC;
    const int bh  = cta % BC;
    const int tid = threadIdx.x;

    __shared__ float sv[WW];

    // padded window [bh*14, bh*14+16) -> unpadded rows [bh*14-1, bh*14+15)
    const int h0 = bh * BSTR - 1;
    const int hs = (h0 < 0) ? 0 : h0;
    const int he = (h0 + BHW < HH) ? (h0 + BHW) : HH;

    const float4* base = (const float4*)(mask + (size_t)n * HH * WW);
    float4 acc = make_float4(0.f, 0.f, 0.f, 0.f);
    for (int h = hs; h < he; ++h) {
        float4 x = base[h * (WW / 4) + tid];
        acc.x = fmaxf(acc.x, x.x);
        acc.y = fmaxf(acc.y, x.y);
        acc.z = fmaxf(acc.z, x.z);
        acc.w = fmaxf(acc.w, x.w);
    }
    sv[4 * tid + 0] = acc.x;
    sv[4 * tid + 1] = acc.y;
    sv[4 * tid + 2] = acc.z;
    sv[4 * tid + 3] = acc.w;
    __syncthreads();

    if (tid < BC) {
        const int w0 = tid * BSTR - 1;
        const int ws = (w0 < 0) ? 0 : w0;
        const int we = (w0 + BHW < WW) ? (w0 + BHW) : WW;
        float m = 0.f;
        for (int w = ws; w < we; ++w) m = fmaxf(m, sv[w]);
        g_flags[cta * BC + tid] = (m > THRESH) ? 1 : 0;
    }
}

// ---------------------------------------------------------------------------
// K2: single-CTA exclusive scan over all NBLK flags (blocked Hillis-Steele).
// ---------------------------------------------------------------------------
#define SCAN_T 256
#define CHUNK  ((NBLK + SCAN_T - 1) / SCAN_T)   // 667

__global__ __launch_bounds__(SCAN_T) void scan_kernel()
{
    __shared__ int partial[SCAN_T];
    const int tid   = threadIdx.x;
    const int start = tid * CHUNK;
    const int end   = (start + CHUNK < NBLK) ? (start + CHUNK) : NBLK;

    int sum = 0;
    for (int i = start; i < end; ++i) sum += g_flags[i];
    partial[tid] = sum;
    __syncthreads();

    for (int off = 1; off < SCAN_T; off <<= 1) {
        int t = (tid >= off) ? partial[tid - off] : 0;
        __syncthreads();
        partial[tid] += t;
        __syncthreads();
    }

    int run = (tid > 0) ? partial[tid - 1] : 0;   // exclusive base for my chunk
    for (int i = start; i < end; ++i) {
        g_pos[i] = run;
        run += g_flags[i];
    }
}

// ---------------------------------------------------------------------------
// K3: scatter. One thread per block index i (row-major over n,bh,bw); active
// blocks write their (n, bh, bw) triple — AS FLOATS — at their scan position.
// Row-major i order == jnp.nonzero emission order.
// ---------------------------------------------------------------------------
__global__ __launch_bounds__(256) void scatter_kernel(float* __restrict__ out)
{
    int i = blockIdx.x * 256 + threadIdx.x;
    if (i >= NBLK) return;
    if (g_flags[i]) {
        int p = g_pos[i];
        if (p >= 0 && p < NBLK) {
            int n = i / (BC * BC);
            int r = i % (BC * BC);
            out[3 * p + 0] = (float)n;
            out[3 * p + 1] = (float)(r / BC);
            out[3 * p + 2] = (float)(r % BC);
        }
    }
}

// ---------------------------------------------------------------------------
extern "C" void kernel_launch(void* const* d_in, const int* in_sizes, int n_in,
                              void* d_out, int out_size)
{
    const float* mask = (const float*)d_in[0];
    float* out = (float*)d_out;

    fill_kernel<<<(OUT_ELEMS + 255) / 256, 256>>>(out);
    pool_kernel<<<NROW, 256>>>(mask);
    scan_kernel<<<1, SCAN_T>>>();
    scatter_kernel<<<(NBLK + 255) / 256, 256>>>(out);
}

// round 4
// speedup vs baseline: 5.8108x; 5.8108x over previous
#include <cuda_runtime.h>
#include <cuda_bf16.h>

// ---- static problem config ----
#define NIMG 32
#define HH   1024
#define WW   1024
#define BHW  16                 // pool window
#define BSTR 14                 // block stride
#define BC   73                 // blocks per spatial dim
#define NROW (NIMG*BC)          // 2336  (n, bh) row-blocks
#define NBLK (NROW*BC)          // 170528 total blocks
#define OUT_ELEMS (NBLK*3)      // 511584 output floats (divisible by 4)
#define THRESH 0.9f

// scratch (device globals — no allocation allowed)
__device__ unsigned g_bitmap[NROW * 3];   // 96-bit active mask per (n,bh) row
__device__ unsigned g_count[NROW];        // popcount per row
__device__ unsigned g_offset[NROW];       // exclusive prefix of counts

// ---------------------------------------------------------------------------
// K0: fill output with -1.0f using float4 stores (2 MB).
// ---------------------------------------------------------------------------
__global__ __launch_bounds__(256) void fill_kernel(float4* __restrict__ out)
{
    int i = blockIdx.x * 256 + threadIdx.x;
    if (i < OUT_ELEMS / 4)
        out[i] = make_float4(-1.f, -1.f, -1.f, -1.f);
}

// ---------------------------------------------------------------------------
// K1: one CTA per (n, bh). 256 threads: vertical max over the <=16-row
// window (coalesced float4, 4 columns/thread) -> smem; then warps 0-2
// (threads 0..95) compute the 73 horizontal window maxima and ballot them
// into a 96-bit bitmap + count. Zero is the exact identity (zero padding,
// mask in [0,1)).
// ---------------------------------------------------------------------------
__global__ __launch_bounds__(256) void pool_kernel(const float* __restrict__ mask)
{
    const int cta = blockIdx.x;          // n*BC + bh
    const int n   = cta / BC;
    const int bh  = cta % BC;
    const int tid = threadIdx.x;

    __shared__ float sv[WW];
    __shared__ unsigned sbm[3];

    // padded window [bh*14, bh*14+16) -> unpadded rows [bh*14-1, bh*14+15)
    const int h0 = bh * BSTR - 1;
    const int hs = (h0 < 0) ? 0 : h0;
    const int he = (h0 + BHW < HH) ? (h0 + BHW) : HH;

    const float4* base = (const float4*)(mask + (size_t)n * HH * WW);
    float4 acc = make_float4(0.f, 0.f, 0.f, 0.f);
    for (int h = hs; h < he; ++h) {
        float4 x = base[h * (WW / 4) + tid];
        acc.x = fmaxf(acc.x, x.x);
        acc.y = fmaxf(acc.y, x.y);
        acc.z = fmaxf(acc.z, x.z);
        acc.w = fmaxf(acc.w, x.w);
    }
    sv[4 * tid + 0] = acc.x;
    sv[4 * tid + 1] = acc.y;
    sv[4 * tid + 2] = acc.z;
    sv[4 * tid + 3] = acc.w;
    __syncthreads();

    if (tid < 96) {                       // warps 0,1,2 participate fully
        float m = 0.f;
        if (tid < BC) {
            const int w0 = tid * BSTR - 1;
            const int ws = (w0 < 0) ? 0 : w0;
            const int we = (w0 + BHW < WW) ? (w0 + BHW) : WW;
            for (int w = ws; w < we; ++w) m = fmaxf(m, sv[w]);
        }
        unsigned b = __ballot_sync(0xFFFFFFFFu, m > THRESH);
        if ((tid & 31) == 0) sbm[tid >> 5] = b;
    }
    __syncthreads();

    if (tid < 3) g_bitmap[cta * 3 + tid] = sbm[tid];
    if (tid == 0)
        g_count[cta] = (unsigned)(__popc(sbm[0]) + __popc(sbm[1]) + __popc(sbm[2]));
}

// ---------------------------------------------------------------------------
// K2: single-CTA exclusive scan over the 2336 per-row counts (tiny).
// ---------------------------------------------------------------------------
#define SCAN_T   256
#define SCAN_PER ((NROW + SCAN_T - 1) / SCAN_T)   // 10

__global__ __launch_bounds__(SCAN_T) void scan_kernel()
{
    __shared__ unsigned partial[SCAN_T];
    const int tid = threadIdx.x;

    unsigned local[SCAN_PER];
    unsigned sum = 0;
    #pragma unroll
    for (int i = 0; i < SCAN_PER; ++i) {
        int idx = tid * SCAN_PER + i;
        unsigned v = (idx < NROW) ? g_count[idx] : 0u;
        local[i] = sum;                 // exclusive within my chunk
        sum += v;
    }
    partial[tid] = sum;
    __syncthreads();

    for (int off = 1; off < SCAN_T; off <<= 1) {
        unsigned t = (tid >= off) ? partial[tid - off] : 0u;
        __syncthreads();
        partial[tid] += t;
        __syncthreads();
    }
    unsigned base = (tid > 0) ? partial[tid - 1] : 0u;

    #pragma unroll
    for (int i = 0; i < SCAN_PER; ++i) {
        int idx = tid * SCAN_PER + i;
        if (idx < NROW) g_offset[idx] = base + local[i];
    }
}

// ---------------------------------------------------------------------------
// K3: scatter. One CTA per (n, bh): rank each active bw via popc of the
// bitmap below its bit, write (n, bh, bw) AS FLOATS at offset+rank.
// Bit order == bw order and row order == (n,bh) order => exact row-major
// jnp.nonzero emission order.
// ---------------------------------------------------------------------------
__global__ __launch_bounds__(96) void scatter_kernel(float* __restrict__ out)
{
    const int cta = blockIdx.x;
    const int n   = cta / BC;
    const int bh  = cta % BC;
    const int tid = threadIdx.x;          // 96 threads; 73 used

    const unsigned w0 = g_bitmap[cta * 3 + 0];
    const unsigned w1 = g_bitmap[cta * 3 + 1];
    const unsigned w2 = g_bitmap[cta * 3 + 2];
    const unsigned base = g_offset[cta];

    if (tid < BC) {
        const int word = tid >> 5;
        const int bit  = tid & 31;
        const unsigned mw = (word == 0) ? w0 : ((word == 1) ? w1 : w2);
        if ((mw >> bit) & 1u) {
            int rank = __popc(mw & ((1u << bit) - 1u));
            if (word > 0) rank += __popc(w0);
            if (word > 1) rank += __popc(w1);
            const unsigned pos = base + (unsigned)rank;
            out[3u * pos + 0] = (float)n;
            out[3u * pos + 1] = (float)bh;
            out[3u * pos + 2] = (float)tid;
        }
    }
}

// ---------------------------------------------------------------------------
extern "C" void kernel_launch(void* const* d_in, const int* in_sizes, int n_in,
                              void* d_out, int out_size)
{
    const float* mask = (const float*)d_in[0];
    float* out = (float*)d_out;

    fill_kernel<<<(OUT_ELEMS / 4 + 255) / 256, 256>>>((float4*)out);
    pool_kernel<<<NROW, 256>>>(mask);
    scan_kernel<<<1, SCAN_T>>>();
    scatter_kernel<<<NROW, 96>>>(out);
}

// round 5
// speedup vs baseline: 5.8585x; 1.0082x over previous
#include <cuda_runtime.h>
#include <cuda_bf16.h>

// ---- static problem config ----
#define NIMG 32
#define HH   1024
#define WW   1024
#define BHW  16                 // pool window
#define BSTR 14                 // block stride
#define BC   73                 // blocks per spatial dim
#define BC2  (BC*BC)            // 5329
#define NROW (NIMG*BC)          // 2336  (n, bh) row-blocks
#define NBLK (NROW*BC)          // 170528 total blocks
#define OUT_ELEMS (NBLK*3)      // 511584 floats = 127896 float4 (exact)
#define OUT_VEC4  (OUT_ELEMS/4)
#define THRESH 0.9f

// scratch (device globals — no allocation allowed)
__device__ unsigned g_bitmap[NROW * 3];   // 96-bit active mask per (n,bh) row
__device__ unsigned g_count[NROW];        // popcount per row
__device__ unsigned g_offset[NROW];       // exclusive prefix of counts
__device__ unsigned g_total;              // total active blocks

// ---------------------------------------------------------------------------
// K1: one CTA per (n, bh). 256 threads: vertical max over the <=16-row
// window (coalesced float4, 4 columns/thread) -> smem; warps 0-2 compute the
// 73 horizontal window maxima and ballot them into a 96-bit bitmap + count.
// Zero is the exact identity (zero padding, mask values in [0,1)).
// ---------------------------------------------------------------------------
__global__ __launch_bounds__(256) void pool_kernel(const float* __restrict__ mask)
{
    const int cta = blockIdx.x;          // n*BC + bh
    const int n   = cta / BC;
    const int bh  = cta % BC;
    const int tid = threadIdx.x;

    __shared__ float sv[WW];
    __shared__ unsigned sbm[3];

    // padded window [bh*14, bh*14+16) -> unpadded rows [bh*14-1, bh*14+15)
    const int h0 = bh * BSTR - 1;
    const int hs = (h0 < 0) ? 0 : h0;
    const int he = (h0 + BHW < HH) ? (h0 + BHW) : HH;

    const float4* base = (const float4*)(mask + (size_t)n * HH * WW);
    float4 acc = make_float4(0.f, 0.f, 0.f, 0.f);
    #pragma unroll 4
    for (int h = hs; h < he; ++h) {
        float4 x = base[h * (WW / 4) + tid];
        acc.x = fmaxf(acc.x, x.x);
        acc.y = fmaxf(acc.y, x.y);
        acc.z = fmaxf(acc.z, x.z);
        acc.w = fmaxf(acc.w, x.w);
    }
    sv[4 * tid + 0] = acc.x;
    sv[4 * tid + 1] = acc.y;
    sv[4 * tid + 2] = acc.z;
    sv[4 * tid + 3] = acc.w;
    __syncthreads();

    if (tid < 96) {                       // warps 0,1,2
        float m = 0.f;
        if (tid < BC) {
            const int w0 = tid * BSTR - 1;
            const int ws = (w0 < 0) ? 0 : w0;
            const int we = (w0 + BHW < WW) ? (w0 + BHW) : WW;
            for (int w = ws; w < we; ++w) m = fmaxf(m, sv[w]);
        }
        unsigned b = __ballot_sync(0xFFFFFFFFu, m > THRESH);
        if ((tid & 31) == 0) sbm[tid >> 5] = b;
    }
    __syncthreads();

    if (tid < 3) g_bitmap[cta * 3 + tid] = sbm[tid];
    if (tid == 0)
        g_count[cta] = (unsigned)(__popc(sbm[0]) + __popc(sbm[1]) + __popc(sbm[2]));
}

// ---------------------------------------------------------------------------
// K2: single-CTA exclusive scan over the 2336 per-row counts; emits g_total.
// ---------------------------------------------------------------------------
#define SCAN_T   256
#define SCAN_PER ((NROW + SCAN_T - 1) / SCAN_T)   // 10

__global__ __launch_bounds__(SCAN_T) void scan_kernel()
{
    __shared__ unsigned partial[SCAN_T];
    const int tid = threadIdx.x;

    unsigned local[SCAN_PER];
    unsigned sum = 0;
    #pragma unroll
    for (int i = 0; i < SCAN_PER; ++i) {
        int idx = tid * SCAN_PER + i;
        unsigned v = (idx < NROW) ? g_count[idx] : 0u;
        local[i] = sum;                 // exclusive within my chunk
        sum += v;
    }
    partial[tid] = sum;
    __syncthreads();

    for (int off = 1; off < SCAN_T; off <<= 1) {
        unsigned t = (tid >= off) ? partial[tid - off] : 0u;
        __syncthreads();
        partial[tid] += t;
        __syncthreads();
    }
    unsigned base = (tid > 0) ? partial[tid - 1] : 0u;

    #pragma unroll
    for (int i = 0; i < SCAN_PER; ++i) {
        int idx = tid * SCAN_PER + i;
        if (idx < NROW) g_offset[idx] = base + local[i];
    }
    if (tid == SCAN_T - 1) g_total = partial[tid];
}

// ---------------------------------------------------------------------------
// Position -> (n, bh, bw) resolution.
// Fast path (total == NBLK, the bench seed's case): identity divmod.
// General path: binary search last row with offset <= p, then select the
// rank-th set bit of that row's 96-bit bitmap.
// ---------------------------------------------------------------------------
__device__ __forceinline__ int nth_set_bit(unsigned w, int n)  // n-th (0-based)
{
    return (int)__fns(w, 0, n + 1);
}

__device__ __forceinline__ void resolve_pos(unsigned p, unsigned total,
                                            float* t /*[3]*/)
{
    if (p >= total) { t[0] = -1.f; t[1] = -1.f; t[2] = -1.f; return; }

    if (total == NBLK) {   // dense: active block index == block index
        unsigned n = p / BC2;
        unsigned r = p - n * BC2;
        t[0] = (float)n;
        t[1] = (float)(r / BC);
        t[2] = (float)(r % BC);
        return;
    }

    // binary search: last row with g_offset[row] <= p
    int lo = 0, hi = NROW - 1;
    while (lo < hi) {
        int mid = (lo + hi + 1) >> 1;
        if (g_offset[mid] <= p) lo = mid; else hi = mid - 1;
    }
    int row = lo;
    int rank = (int)(p - g_offset[row]);

    unsigned w0 = g_bitmap[row * 3 + 0];
    unsigned w1 = g_bitmap[row * 3 + 1];
    unsigned w2 = g_bitmap[row * 3 + 2];
    int c0 = __popc(w0), c1 = __popc(w1);
    int bw;
    if (rank < c0)            bw = nth_set_bit(w0, rank);
    else if (rank - c0 < c1)  bw = 32 + nth_set_bit(w1, rank - c0);
    else                      bw = 64 + nth_set_bit(w2, rank - c0 - c1);

    t[0] = (float)(row / BC);
    t[1] = (float)(row % BC);
    t[2] = (float)bw;
}

// ---------------------------------------------------------------------------
// K3: output-driven write. One thread per float4 output slot (4 elements,
// spanning at most 2 consecutive positions p0, p0+1). Fully dense coalesced
// 16B stores; tail (-1 padding) handled in the same pass — no fill kernel.
// ---------------------------------------------------------------------------
__global__ __launch_bounds__(256) void write_kernel(float4* __restrict__ out)
{
    const int slot = blockIdx.x * 256 + threadIdx.x;
    if (slot >= OUT_VEC4) return;

    const unsigned total = g_total;
    const unsigned e0 = (unsigned)slot * 4u;
    const unsigned p0 = e0 / 3u;

    float t0[3], t1[3];
    resolve_pos(p0, total, t0);
    resolve_pos(p0 + 1u, total, t1);

    float v[4];
    #pragma unroll
    for (int k = 0; k < 4; ++k) {
        unsigned e = e0 + (unsigned)k;
        unsigned p = e / 3u;
        unsigned c = e - p * 3u;
        v[k] = (p == p0) ? t0[c] : t1[c];
    }
    out[slot] = make_float4(v[0], v[1], v[2], v[3]);
}

// ---------------------------------------------------------------------------
extern "C" void kernel_launch(void* const* d_in, const int* in_sizes, int n_in,
                              void* d_out, int out_size)
{
    const float* mask = (const float*)d_in[0];

    pool_kernel<<<NROW, 256>>>(mask);
    scan_kernel<<<1, SCAN_T>>>();
    write_kernel<<<(OUT_VEC4 + 255) / 256, 256>>>((float4*)d_out);
}